// round 2
// baseline (speedup 1.0000x reference)
#include <cuda_runtime.h>

#define HDIM 64
#define IDIM 2
#define TOUT 50
#define TPB  256

// ---------------- packed f32x2 helpers (Blackwell f32x2 pipe) ----------------
__device__ __forceinline__ unsigned long long pk2(float lo, float hi) {
    unsigned long long r;
    asm("mov.b64 %0, {%1, %2};" : "=l"(r) : "f"(lo), "f"(hi));
    return r;
}
__device__ __forceinline__ float hadd2(unsigned long long v) {
    float lo, hi;
    asm("mov.b64 {%0, %1}, %2;" : "=f"(lo), "=f"(hi) : "l"(v));
    return lo + hi;
}
__device__ __forceinline__ unsigned long long ffma2(unsigned long long a,
                                                    unsigned long long b,
                                                    unsigned long long c) {
    unsigned long long d;
    asm("fma.rn.f32x2 %0, %1, %2, %3;" : "=l"(d) : "l"(a), "l"(b), "l"(c));
    return d;
}

// ---------------- fast activations (abs err ~1e-7, fine for 1e-3 gate) -------
__device__ __forceinline__ float fsig(float x) {
    return __fdividef(1.0f, 1.0f + __expf(-x));
}
__device__ __forceinline__ float ftanh_(float x) {
    float e = __expf(2.0f * x);
    return 1.0f - __fdividef(2.0f, e + 1.0f);
}

// ---------------- shared memory layout ----------------
// w4  : Whh rearranged as [j][gate][k4]  -> broadcast LDS.128 in the hot loop
// bc4 : (bih+bhh) per j, gates packed in float4 (i,f,g,o)
// wx0/wx1 : Wih columns 0/1, same packing
// hscr/cscr : per-thread h/c columns, [j][tid] -> conflict-free
struct __align__(16) Smem {
    float4 w4[HDIM * 4 * 16];   // 64 KB
    float4 bc4[HDIM];           // 1 KB
    float4 wx0[HDIM];           // 1 KB
    float4 wx1[HDIM];           // 1 KB
    float  wfc[2 * HDIM];       // 512 B
    float  bfc[2];
    float  pad[2];
    float  hscr[HDIM * TPB];    // 64 KB
    float  cscr[HDIM * TPB];    // 64 KB
};

__device__ void load_phase_weights(Smem* S, const float* __restrict__ Whh,
                                   const float* __restrict__ Wih,
                                   const float* __restrict__ bih,
                                   const float* __restrict__ bhh, int tid) {
    const float4* whh4 = (const float4*)Whh;   // Whh row-major (256, 64), 16 float4/row
    for (int idx = tid; idx < HDIM * 4 * 16; idx += TPB) {
        int kc = idx & 15;
        int g  = (idx >> 4) & 3;
        int j  = idx >> 6;
        S->w4[idx] = whh4[(g * HDIM + j) * 16 + kc];
    }
    for (int j = tid; j < HDIM; j += TPB) {
        S->bc4[j] = make_float4(bih[j]          + bhh[j],
                                bih[j + 64]     + bhh[j + 64],
                                bih[j + 128]    + bhh[j + 128],
                                bih[j + 192]    + bhh[j + 192]);
        S->wx0[j] = make_float4(Wih[2 * j],        Wih[2 * (j + 64)],
                                Wih[2 * (j + 128)], Wih[2 * (j + 192)]);
        S->wx1[j] = make_float4(Wih[2 * j + 1],        Wih[2 * (j + 64) + 1],
                                Wih[2 * (j + 128) + 1], Wih[2 * (j + 192) + 1]);
    }
}

// One LSTM cell step for this thread's batch element.
// h2: packed old hidden state (32 x f32x2 registers). c lives in S->cscr column.
__device__ __forceinline__ void lstm_step(unsigned long long h2[32], Smem* S,
                                          float x0, float x1, int tid) {
#pragma unroll 1
    for (int j = 0; j < HDIM; j++) {
        const ulonglong2* wp = (const ulonglong2*)(S->w4 + j * 64);
        unsigned long long ai = 0ULL, af = 0ULL, ag = 0ULL, ao = 0ULL;
#pragma unroll
        for (int kc = 0; kc < 16; kc++) {
            ulonglong2 wi = wp[kc];
            ulonglong2 wf = wp[16 + kc];
            ulonglong2 wg = wp[32 + kc];
            ulonglong2 wo = wp[48 + kc];
            unsigned long long he = h2[2 * kc];
            unsigned long long ho = h2[2 * kc + 1];
            ai = ffma2(wi.x, he, ai);  ai = ffma2(wi.y, ho, ai);
            af = ffma2(wf.x, he, af);  af = ffma2(wf.y, ho, af);
            ag = ffma2(wg.x, he, ag);  ag = ffma2(wg.y, ho, ag);
            ao = ffma2(wo.x, he, ao);  ao = ffma2(wo.y, ho, ao);
        }
        float4 bcv = S->bc4[j];
        float4 w0v = S->wx0[j];
        float4 w1v = S->wx1[j];
        float gi = hadd2(ai) + fmaf(x1, w1v.x, fmaf(x0, w0v.x, bcv.x));
        float gf = hadd2(af) + fmaf(x1, w1v.y, fmaf(x0, w0v.y, bcv.y));
        float gg = hadd2(ag) + fmaf(x1, w1v.z, fmaf(x0, w0v.z, bcv.z));
        float go = hadd2(ao) + fmaf(x1, w1v.w, fmaf(x0, w0v.w, bcv.w));

        float ii = fsig(gi);
        float ff = fsig(gf);
        float gt = ftanh_(gg);
        float oo = fsig(go);

        float cold = S->cscr[j * TPB + tid];
        float cn = fmaf(ff, cold, ii * gt);
        S->cscr[j * TPB + tid] = cn;
        S->hscr[j * TPB + tid] = oo * ftanh_(cn);
    }
    // repack new h into registers (own column only: no sync needed)
#pragma unroll
    for (int k = 0; k < 32; k++) {
        h2[k] = pk2(S->hscr[(2 * k) * TPB + tid], S->hscr[(2 * k + 1) * TPB + tid]);
    }
}

__global__ void __launch_bounds__(TPB, 1)
seq2seq_lstm_kernel(const float* __restrict__ input,
                    const float* __restrict__ Wih_enc, const float* __restrict__ Whh_enc,
                    const float* __restrict__ bih_enc, const float* __restrict__ bhh_enc,
                    const float* __restrict__ Wih_dec, const float* __restrict__ Whh_dec,
                    const float* __restrict__ bih_dec, const float* __restrict__ bhh_dec,
                    const float* __restrict__ Wfc,     const float* __restrict__ bfc,
                    float* __restrict__ out, int B, int T) {
    extern __shared__ char smem_raw[];
    Smem* S = (Smem*)smem_raw;
    int tid = threadIdx.x;
    long b = (long)blockIdx.x * TPB + tid;
    bool valid = b < B;
    long bcl = valid ? b : (long)(B - 1);

    // ---- encoder weights + fc weights into SMEM ----
    load_phase_weights(S, Whh_enc, Wih_enc, bih_enc, bhh_enc, tid);
    for (int i = tid; i < 2 * HDIM; i += TPB) S->wfc[i] = Wfc[i];
    if (tid < 2) S->bfc[tid] = bfc[tid];
    __syncthreads();

    // ---- zero state ----
    unsigned long long h2[32];
#pragma unroll
    for (int k = 0; k < 32; k++) h2[k] = 0ULL;
#pragma unroll 1
    for (int j = 0; j < HDIM; j++) S->cscr[j * TPB + tid] = 0.0f;

    // ---- encoder ----
    const float* xptr = input + bcl * (long)T * IDIM;
    float x0 = 0.0f, x1 = 0.0f;
#pragma unroll 1
    for (int t = 0; t < T; t++) {
        float2 xv = *(const float2*)(xptr + (long)t * IDIM);
        x0 = xv.x;
        x1 = xv.y;
        lstm_step(h2, S, x0, x1, tid);
    }

    // ---- swap in decoder weights ----
    __syncthreads();
    load_phase_weights(S, Whh_dec, Wih_dec, bih_dec, bhh_dec, tid);
    __syncthreads();

    // ---- decoder: x starts at last encoder input (dec_in0) ----
    float* optr = out + bcl * (long)TOUT * IDIM;
#pragma unroll 1
    for (int t = 0; t < TOUT; t++) {
        lstm_step(h2, S, x0, x1, tid);
        // fc head: point = sigmoid(h @ Wfc.T + bfc)
        const unsigned long long* w0 = (const unsigned long long*)S->wfc;
        const unsigned long long* w1 = (const unsigned long long*)(S->wfc + HDIM);
        unsigned long long a0 = 0ULL, a1 = 0ULL;
#pragma unroll
        for (int k = 0; k < 32; k++) {
            a0 = ffma2(w0[k], h2[k], a0);
            a1 = ffma2(w1[k], h2[k], a1);
        }
        float p0 = fsig(hadd2(a0) + S->bfc[0]);
        float p1 = fsig(hadd2(a1) + S->bfc[1]);
        if (valid) {
            float2 pv = make_float2(p0, p1);
            *(float2*)(optr + (long)t * IDIM) = pv;
        }
        x0 = p0;
        x1 = p1;
    }
}

extern "C" void kernel_launch(void* const* d_in, const int* in_sizes, int n_in,
                              void* d_out, int out_size) {
    const float* input   = (const float*)d_in[0];
    const float* Wih_enc = (const float*)d_in[1];
    const float* Whh_enc = (const float*)d_in[2];
    const float* bih_enc = (const float*)d_in[3];
    const float* bhh_enc = (const float*)d_in[4];
    const float* Wih_dec = (const float*)d_in[5];
    const float* Whh_dec = (const float*)d_in[6];
    const float* bih_dec = (const float*)d_in[7];
    const float* bhh_dec = (const float*)d_in[8];
    const float* Wfc     = (const float*)d_in[9];
    const float* bfc     = (const float*)d_in[10];
    float* out = (float*)d_out;

    int B = out_size / (TOUT * IDIM);
    int T = in_sizes[0] / (B * IDIM);

    size_t smem = sizeof(Smem);
    cudaFuncSetAttribute(seq2seq_lstm_kernel,
                         cudaFuncAttributeMaxDynamicSharedMemorySize, (int)smem);

    int grid = (B + TPB - 1) / TPB;
    seq2seq_lstm_kernel<<<grid, TPB, smem>>>(
        input, Wih_enc, Whh_enc, bih_enc, bhh_enc,
        Wih_dec, Whh_dec, bih_dec, bhh_dec, Wfc, bfc,
        out, B, T);
}

// round 4
// speedup vs baseline: 2.5185x; 2.5185x over previous
#include <cuda_runtime.h>
#include <cuda_bf16.h>
#include <cstdint>

#define TPB  128
#define TOUT 50

// ---- SMEM layout (byte offsets from 1024-aligned base) ----
#define OFF_BHI 0        // Whh hi  : 256 rows x 128B, SW128-swizzled   32 KB
#define OFF_BLO 32768    // Whh lo  : 256 rows x 128B                    32 KB
#define OFF_A   65536    // per warp: hi @ OFF_A + wid*8192, lo @ +4096  32 KB
#define OFF_BC4 98304    // float4[64] (bih+bhh) gates (i,f,g,o)          1 KB
#define OFF_WX0 99328    // float4[64] Wih col 0                          1 KB
#define OFF_WX1 100352   // float4[64] Wih col 1                          1 KB
#define OFF_WFC 101376   // float[128]
#define OFF_BFC 101888   // float[2]
#define SMEM_BYTES (101920 + 1024)

__device__ __forceinline__ float fsig(float x)   { return __fdividef(1.0f, 1.0f + __expf(-x)); }
__device__ __forceinline__ float ftanh_(float x) { float e = __expf(2.0f * x); return 1.0f - __fdividef(2.0f, e + 1.0f); }

#define LDSM_X4(r0, r1, r2, r3, addr) \
    asm volatile("ldmatrix.sync.aligned.m8n8.x4.shared.b16 {%0,%1,%2,%3}, [%4];" \
        : "=r"(r0), "=r"(r1), "=r"(r2), "=r"(r3) : "r"(addr))

#define MMA_BF16(d, a, b0, b1) \
    asm volatile("mma.sync.aligned.m16n8k16.row.col.f32.bf16.bf16.f32 " \
        "{%0,%1,%2,%3}, {%4,%5,%6,%7}, {%8,%9}, {%0,%1,%2,%3};" \
        : "+f"((d)[0]), "+f"((d)[1]), "+f"((d)[2]), "+f"((d)[3]) \
        : "r"((a)[0]), "r"((a)[1]), "r"((a)[2]), "r"((a)[3]), "r"(b0), "r"(b1))

#define STS32(addr, v) asm volatile("st.shared.b32 [%0], %1;" :: "r"(addr), "r"(v))

// ---------------- weight staging (per phase) ----------------
// Whh (256,64) fp32 -> SMEM bf16 hi/lo, row n = gate*64+j, SW128 swizzle.
__device__ void load_phase(char* sm, const float* __restrict__ Whh,
                           const float* __restrict__ Wih,
                           const float* __restrict__ bih,
                           const float* __restrict__ bhh, int tid) {
    for (int idx = tid; idx < 256 * 64; idx += TPB) {
        int k = idx & 63;
        int n = idx >> 6;
        float w = Whh[idx];
        __nv_bfloat16 hi = __float2bfloat16(w);
        float lof = w - __bfloat162float(hi);
        __nv_bfloat16 lo = __float2bfloat16(lof);
        uint32_t off = (uint32_t)n * 128u + (((uint32_t)k * 2u) ^ (uint32_t)((n & 7) << 4));
        *(__nv_bfloat16*)(sm + OFF_BHI + off) = hi;
        *(__nv_bfloat16*)(sm + OFF_BLO + off) = lo;
    }
    float4* bc4 = (float4*)(sm + OFF_BC4);
    float4* wx0 = (float4*)(sm + OFF_WX0);
    float4* wx1 = (float4*)(sm + OFF_WX1);
    for (int j = tid; j < 64; j += TPB) {
        bc4[j] = make_float4(bih[j]       + bhh[j],
                             bih[j + 64]  + bhh[j + 64],
                             bih[j + 128] + bhh[j + 128],
                             bih[j + 192] + bhh[j + 192]);
        wx0[j] = make_float4(Wih[2 * j],         Wih[2 * (j + 64)],
                             Wih[2 * (j + 128)], Wih[2 * (j + 192)]);
        wx1[j] = make_float4(Wih[2 * j + 1],         Wih[2 * (j + 64) + 1],
                             Wih[2 * (j + 128) + 1], Wih[2 * (j + 192) + 1]);
    }
}

// ---------------- one LSTM step (per warp, 32 batch rows) ----------------
template<bool DEC>
__device__ __forceinline__ void lstm_step(uint32_t smu, const char* sm,
                                          uint32_t aHi, uint32_t aLo,
                                          const float2 x[4], float c[4][16],
                                          float2 pt[4], int lane)
{
    __syncwarp();   // previous step's STS of h visible to ldmatrix (cross-lane)

    // ---- A fragments: h hi/lo, 32 rows x 64 k ----
    uint32_t ahi[2][4][4], alo[2][4][4];
    {
        uint32_t arow = (uint32_t)(lane & 15) * 128u;
        uint32_t amsk = (uint32_t)(lane & 7) << 4;
        uint32_t ainr = (uint32_t)(lane >> 4) * 16u;
#pragma unroll
        for (int mt = 0; mt < 2; mt++) {
#pragma unroll
            for (int kc = 0; kc < 4; kc++) {
                uint32_t col = ((uint32_t)(kc * 32) + ainr) ^ amsk;
                LDSM_X4(ahi[mt][kc][0], ahi[mt][kc][1], ahi[mt][kc][2], ahi[mt][kc][3],
                        aHi + (uint32_t)mt * 2048u + arow + col);
                LDSM_X4(alo[mt][kc][0], alo[mt][kc][1], alo[mt][kc][2], alo[mt][kc][3],
                        aLo + (uint32_t)mt * 2048u + arow + col);
            }
        }
    }

    const float4* bc4 = (const float4*)(sm + OFF_BC4);
    const float4* wx0 = (const float4*)(sm + OFF_WX0);
    const float4* wx1 = (const float4*)(sm + OFF_WX1);
    const float*  wfc = (const float*)(sm + OFF_WFC);

    float fc0[4] = {0.f, 0.f, 0.f, 0.f};
    float fc1[4] = {0.f, 0.f, 0.f, 0.f};

    uint32_t brow = (uint32_t)(lane & 7) * 128u;
    uint32_t bmsk = (uint32_t)(lane & 7) << 4;
    uint32_t binr = (uint32_t)(lane >> 3) * 16u;

#pragma unroll
    for (int jb = 0; jb < 8; jb++) {
        float d[4][2][4];
#pragma unroll
        for (int g = 0; g < 4; g++)
#pragma unroll
            for (int mt = 0; mt < 2; mt++)
#pragma unroll
                for (int e = 0; e < 4; e++) d[g][mt][e] = 0.0f;

        // ---- MMAs: D = Ahi@Bhi + Alo@Bhi + Ahi@Blo ----
#pragma unroll
        for (int p = 0; p < 2; p++) {
            uint32_t bcol = ((uint32_t)(p * 64) + binr) ^ bmsk;
#pragma unroll
            for (int g = 0; g < 4; g++) {
                uint32_t roff = (uint32_t)((g * 64 + jb * 8) * 128) + brow;
                uint32_t b0, b1, b2, b3;
                LDSM_X4(b0, b1, b2, b3, smu + OFF_BHI + roff + bcol);
#pragma unroll
                for (int mt = 0; mt < 2; mt++) {
                    MMA_BF16(d[g][mt], ahi[mt][2 * p],     b0, b1);
                    MMA_BF16(d[g][mt], ahi[mt][2 * p + 1], b2, b3);
                    MMA_BF16(d[g][mt], alo[mt][2 * p],     b0, b1);
                    MMA_BF16(d[g][mt], alo[mt][2 * p + 1], b2, b3);
                }
                LDSM_X4(b0, b1, b2, b3, smu + OFF_BLO + roff + bcol);
#pragma unroll
                for (int mt = 0; mt < 2; mt++) {
                    MMA_BF16(d[g][mt], ahi[mt][2 * p],     b0, b1);
                    MMA_BF16(d[g][mt], ahi[mt][2 * p + 1], b2, b3);
                }
            }
        }

        // ---- epilogue: this thread owns j0, j0+1 for 4 rows ----
        int j0 = jb * 8 + (lane & 3) * 2;
        float4 bcA = bc4[j0], bcB = bc4[j0 + 1];
        float4 w0A = wx0[j0], w0B = wx0[j0 + 1];
        float4 w1A = wx1[j0], w1B = wx1[j0 + 1];
        float wfA0 = 0.f, wfB0 = 0.f, wfA1 = 0.f, wfB1 = 0.f;
        if (DEC) {
            wfA0 = wfc[j0]; wfB0 = wfc[j0 + 1];
            wfA1 = wfc[64 + j0]; wfB1 = wfc[64 + j0 + 1];
        }
        uint32_t q    = (uint32_t)(lane >> 2);
        uint32_t colb = ((uint32_t)(jb * 16 + (lane & 3) * 4)) ^ (q << 4);
#pragma unroll
        for (int i = 0; i < 4; i++) {
            int mt = i >> 1;
            int e  = (i & 1) * 2;
            float x0 = x[i].x, x1 = x[i].y;

            float gi = d[0][mt][e] + fmaf(x1, w1A.x, fmaf(x0, w0A.x, bcA.x));
            float gf = d[1][mt][e] + fmaf(x1, w1A.y, fmaf(x0, w0A.y, bcA.y));
            float gg = d[2][mt][e] + fmaf(x1, w1A.z, fmaf(x0, w0A.z, bcA.z));
            float go = d[3][mt][e] + fmaf(x1, w1A.w, fmaf(x0, w0A.w, bcA.w));
            float c0 = fmaf(fsig(gf), c[i][jb * 2], fsig(gi) * ftanh_(gg));
            c[i][jb * 2] = c0;
            float h0 = fsig(go) * ftanh_(c0);

            gi = d[0][mt][e + 1] + fmaf(x1, w1B.x, fmaf(x0, w0B.x, bcB.x));
            gf = d[1][mt][e + 1] + fmaf(x1, w1B.y, fmaf(x0, w0B.y, bcB.y));
            gg = d[2][mt][e + 1] + fmaf(x1, w1B.z, fmaf(x0, w0B.z, bcB.z));
            go = d[3][mt][e + 1] + fmaf(x1, w1B.w, fmaf(x0, w0B.w, bcB.w));
            float c1 = fmaf(fsig(gf), c[i][jb * 2 + 1], fsig(gi) * ftanh_(gg));
            c[i][jb * 2 + 1] = c1;
            float h1 = fsig(go) * ftanh_(c1);

            if (DEC) {
                fc0[i] = fmaf(h0, wfA0, fmaf(h1, wfB0, fc0[i]));
                fc1[i] = fmaf(h0, wfA1, fmaf(h1, wfB1, fc1[i]));
            }

            // bf16 hi/lo split, pack j-pair, STS into A buffer (swizzled)
            __nv_bfloat16 bh0 = __float2bfloat16(h0);
            __nv_bfloat16 bh1 = __float2bfloat16(h1);
            float r0 = h0 - __bfloat162float(bh0);
            float r1 = h1 - __bfloat162float(bh1);
            __nv_bfloat16 bl0 = __float2bfloat16(r0);
            __nv_bfloat16 bl1 = __float2bfloat16(r1);
            uint32_t hpk = (uint32_t)__bfloat16_as_ushort(bh0) |
                           ((uint32_t)__bfloat16_as_ushort(bh1) << 16);
            uint32_t lpk = (uint32_t)__bfloat16_as_ushort(bl0) |
                           ((uint32_t)__bfloat16_as_ushort(bl1) << 16);
            uint32_t rowoff = (q + (uint32_t)i * 8u) * 128u;
            STS32(aHi + rowoff + colb, hpk);
            STS32(aLo + rowoff + colb, lpk);
        }
    }

    if (DEC) {
        // reduce fc partials across the lane-quad (lanes differ only in j subset)
#pragma unroll
        for (int i = 0; i < 4; i++) {
            fc0[i] += __shfl_xor_sync(0xffffffffu, fc0[i], 1);
            fc0[i] += __shfl_xor_sync(0xffffffffu, fc0[i], 2);
            fc1[i] += __shfl_xor_sync(0xffffffffu, fc1[i], 1);
            fc1[i] += __shfl_xor_sync(0xffffffffu, fc1[i], 2);
            pt[i] = make_float2(fc0[i], fc1[i]);
        }
    }
}

// ---------------- kernel ----------------
__global__ void __launch_bounds__(TPB)
seq2seq_mma_kernel(const float* __restrict__ input,
                   const float* __restrict__ Wih_enc, const float* __restrict__ Whh_enc,
                   const float* __restrict__ bih_enc, const float* __restrict__ bhh_enc,
                   const float* __restrict__ Wih_dec, const float* __restrict__ Whh_dec,
                   const float* __restrict__ bih_dec, const float* __restrict__ bhh_dec,
                   const float* __restrict__ Wfc,     const float* __restrict__ bfc,
                   float* __restrict__ out, int B, int T) {
    extern __shared__ char smem_raw[];
    char* sm;
    {
        unsigned long long p = (unsigned long long)smem_raw;
        p = (p + 1023ull) & ~1023ull;
        sm = (char*)p;
    }
    uint32_t smu;
    asm("{ .reg .u64 t; cvta.to.shared.u64 t, %1; cvt.u32.u64 %0, t; }" : "=r"(smu) : "l"(sm));

    int tid  = threadIdx.x;
    int wid  = tid >> 5;
    int lane = tid & 31;

    // stage encoder weights + fc head
    load_phase(sm, Whh_enc, Wih_enc, bih_enc, bhh_enc, tid);
    {
        float* w = (float*)(sm + OFF_WFC);
        for (int i = tid; i < 128; i += TPB) w[i] = Wfc[i];
        if (tid < 2) ((float*)(sm + OFF_BFC))[tid] = bfc[tid];
    }
    // zero all A buffers (h0 = 0)
    for (int i = tid; i < 32768 / 4; i += TPB) ((uint32_t*)(sm + OFF_A))[i] = 0u;
    __syncthreads();

    uint32_t aHi = smu + OFF_A + (uint32_t)wid * 8192u;
    uint32_t aLo = aHi + 4096u;

    float c[4][16];
#pragma unroll
    for (int i = 0; i < 4; i++)
#pragma unroll
        for (int j = 0; j < 16; j++) c[i][j] = 0.0f;

    int q = lane >> 2;
    long rows[4];
    bool rv[4];
#pragma unroll
    for (int i = 0; i < 4; i++) {
        long r = (long)blockIdx.x * TPB + wid * 32 + q + i * 8;
        rv[i] = r < (long)B;
        rows[i] = rv[i] ? r : (long)(B - 1);
    }

    float2 x[4];
    float2 pt[4];

    // ---- encoder ----
#pragma unroll 1
    for (int t = 0; t < T; t++) {
#pragma unroll
        for (int i = 0; i < 4; i++)
            x[i] = *(const float2*)(input + rows[i] * (long)T * 2 + (long)t * 2);
        lstm_step<false>(smu, sm, aHi, aLo, x, c, pt, lane);
    }

    // ---- swap to decoder weights ----
    __syncthreads();
    load_phase(sm, Whh_dec, Wih_dec, bih_dec, bhh_dec, tid);
    __syncthreads();

    float bf0 = ((const float*)(sm + OFF_BFC))[0];
    float bf1 = ((const float*)(sm + OFF_BFC))[1];

    // ---- decoder (x currently = input[:, T-1] = dec_in0) ----
#pragma unroll 1
    for (int t = 0; t < TOUT; t++) {
        lstm_step<true>(smu, sm, aHi, aLo, x, c, pt, lane);
#pragma unroll
        for (int i = 0; i < 4; i++) {
            float p0 = fsig(pt[i].x + bf0);
            float p1 = fsig(pt[i].y + bf1);
            if ((lane & 3) == 0 && rv[i])
                *(float2*)(out + rows[i] * (long)TOUT * 2 + (long)t * 2) = make_float2(p0, p1);
            x[i] = make_float2(p0, p1);
        }
    }
}

extern "C" void kernel_launch(void* const* d_in, const int* in_sizes, int n_in,
                              void* d_out, int out_size) {
    const float* input   = (const float*)d_in[0];
    const float* Wih_enc = (const float*)d_in[1];
    const float* Whh_enc = (const float*)d_in[2];
    const float* bih_enc = (const float*)d_in[3];
    const float* bhh_enc = (const float*)d_in[4];
    const float* Wih_dec = (const float*)d_in[5];
    const float* Whh_dec = (const float*)d_in[6];
    const float* bih_dec = (const float*)d_in[7];
    const float* bhh_dec = (const float*)d_in[8];
    const float* Wfc     = (const float*)d_in[9];
    const float* bfc     = (const float*)d_in[10];
    float* out = (float*)d_out;

    int B = out_size / (TOUT * 2);
    int T = in_sizes[0] / (B * 2);

    cudaFuncSetAttribute(seq2seq_mma_kernel,
                         cudaFuncAttributeMaxDynamicSharedMemorySize, SMEM_BYTES);

    int grid = (B + TPB - 1) / TPB;
    seq2seq_mma_kernel<<<grid, TPB, SMEM_BYTES>>>(
        input, Wih_enc, Whh_enc, bih_enc, bhh_enc,
        Wih_dec, Whh_dec, bih_dec, bhh_dec, Wfc, bfc,
        out, B, T);
}

// round 5
// speedup vs baseline: 5.3546x; 2.1261x over previous
#include <cuda_runtime.h>
#include <cuda_fp16.h>
#include <cstdint>

#define TPB  256
#define TOUT 50

// ---- SMEM layout (byte offsets from 1024-aligned base) ----
#define OFF_BHI 0        // Whh fp16 : 256 rows x 128B, SW128-swizzled  32 KB
#define OFF_A   32768    // per warp 4KB: hi @ +wid*4096, lo @ +2048    32 KB
#define OFF_BC4 65536    // float4[64] (bih+bhh) gates (i,f,g,o)         1 KB
#define OFF_WX0 66560    // float4[64] Wih col 0                         1 KB
#define OFF_WX1 67584    // float4[64] Wih col 1                         1 KB
#define OFF_WFC 68608    // float[128]
#define OFF_BFC 69120    // float[2]
#define SMEM_BYTES (69128 + 1080)

__device__ __forceinline__ float tanh_a(float x) {
    float y;
    asm("tanh.approx.f32 %0, %1;" : "=f"(y) : "f"(x));
    return y;
}
__device__ __forceinline__ float fsig(float x) { return fmaf(0.5f, tanh_a(0.5f * x), 0.5f); }

#define LDSM_X4(r0, r1, r2, r3, addr) \
    asm volatile("ldmatrix.sync.aligned.m8n8.x4.shared.b16 {%0,%1,%2,%3}, [%4];" \
        : "=r"(r0), "=r"(r1), "=r"(r2), "=r"(r3) : "r"(addr))

#define MMA_FP16(d, a, b0, b1) \
    asm volatile("mma.sync.aligned.m16n8k16.row.col.f32.f16.f16.f32 " \
        "{%0,%1,%2,%3}, {%4,%5,%6,%7}, {%8,%9}, {%0,%1,%2,%3};" \
        : "+f"((d)[0]), "+f"((d)[1]), "+f"((d)[2]), "+f"((d)[3]) \
        : "r"((a)[0]), "r"((a)[1]), "r"((a)[2]), "r"((a)[3]), "r"(b0), "r"(b1))

#define STS32(addr, v) asm volatile("st.shared.b32 [%0], %1;" :: "r"(addr), "r"(v))

// ---------------- weight staging (per phase) ----------------
// Whh (256,64) fp32 -> SMEM fp16, row n = gate*64+j, SW128 swizzle.
__device__ void load_phase(char* sm, const float* __restrict__ Whh,
                           const float* __restrict__ Wih,
                           const float* __restrict__ bih,
                           const float* __restrict__ bhh, int tid) {
    for (int idx = tid; idx < 256 * 64; idx += TPB) {
        int k = idx & 63;
        int n = idx >> 6;
        uint32_t off = (uint32_t)n * 128u + (((uint32_t)k * 2u) ^ (uint32_t)((n & 7) << 4));
        *(__half*)(sm + OFF_BHI + off) = __float2half_rn(Whh[idx]);
    }
    float4* bc4 = (float4*)(sm + OFF_BC4);
    float4* wx0 = (float4*)(sm + OFF_WX0);
    float4* wx1 = (float4*)(sm + OFF_WX1);
    for (int j = tid; j < 64; j += TPB) {
        bc4[j] = make_float4(bih[j]       + bhh[j],
                             bih[j + 64]  + bhh[j + 64],
                             bih[j + 128] + bhh[j + 128],
                             bih[j + 192] + bhh[j + 192]);
        wx0[j] = make_float4(Wih[2 * j],         Wih[2 * (j + 64)],
                             Wih[2 * (j + 128)], Wih[2 * (j + 192)]);
        wx1[j] = make_float4(Wih[2 * j + 1],         Wih[2 * (j + 64) + 1],
                             Wih[2 * (j + 128) + 1], Wih[2 * (j + 192) + 1]);
    }
}

// ---------------- one LSTM step (per warp, 16 batch rows) ----------------
// D[16,256] = h_exact[16,64] @ Whh_fp16^T :  Ahi@Bhi + Alo@Bhi
template<bool DEC>
__device__ __forceinline__ void lstm_step(uint32_t smu, const char* sm,
                                          uint32_t aHi, uint32_t aLo,
                                          const float2 x[2], float c[2][16],
                                          float2 pt[2], int lane)
{
    __syncwarp();   // previous step's STS of h visible to ldmatrix

    // ---- A fragments: h hi/lo, 16 rows x 64 k ----
    uint32_t ahi[4][4], alo[4][4];
    {
        uint32_t arow = (uint32_t)(lane & 15) * 128u;
        uint32_t amsk = (uint32_t)(lane & 7) << 4;
        uint32_t ainr = (uint32_t)(lane >> 4) * 16u;
#pragma unroll
        for (int kc = 0; kc < 4; kc++) {
            uint32_t col = ((uint32_t)(kc * 32) + ainr) ^ amsk;
            LDSM_X4(ahi[kc][0], ahi[kc][1], ahi[kc][2], ahi[kc][3], aHi + arow + col);
            LDSM_X4(alo[kc][0], alo[kc][1], alo[kc][2], alo[kc][3], aLo + arow + col);
        }
    }

    const float4* bc4 = (const float4*)(sm + OFF_BC4);
    const float4* wx0 = (const float4*)(sm + OFF_WX0);
    const float4* wx1 = (const float4*)(sm + OFF_WX1);
    const float*  wfc = (const float*)(sm + OFF_WFC);

    float fc0[2] = {0.f, 0.f};
    float fc1[2] = {0.f, 0.f};

    uint32_t brow = (uint32_t)(lane & 7) * 128u;
    uint32_t bmsk = (uint32_t)(lane & 7) << 4;
    uint32_t binr = (uint32_t)(lane >> 3) * 16u;
    uint32_t q    = (uint32_t)(lane >> 2);

#pragma unroll
    for (int jb = 0; jb < 8; jb++) {
        float d[4][4];
#pragma unroll
        for (int g = 0; g < 4; g++)
#pragma unroll
            for (int e = 0; e < 4; e++) d[g][e] = 0.0f;

#pragma unroll
        for (int p = 0; p < 2; p++) {
            uint32_t bcol = ((uint32_t)(p * 64) + binr) ^ bmsk;
#pragma unroll
            for (int g = 0; g < 4; g++) {
                uint32_t roff = (uint32_t)((g * 64 + jb * 8) * 128) + brow;
                uint32_t b0, b1, b2, b3;
                LDSM_X4(b0, b1, b2, b3, smu + OFF_BHI + roff + bcol);
                MMA_FP16(d[g], ahi[2 * p],     b0, b1);
                MMA_FP16(d[g], ahi[2 * p + 1], b2, b3);
                MMA_FP16(d[g], alo[2 * p],     b0, b1);
                MMA_FP16(d[g], alo[2 * p + 1], b2, b3);
            }
        }

        // ---- epilogue: thread owns (j0, j0+1) x rows (q, q+8) ----
        int j0 = jb * 8 + (lane & 3) * 2;
        float4 bcA = bc4[j0], bcB = bc4[j0 + 1];
        float4 w0A = wx0[j0], w0B = wx0[j0 + 1];
        float4 w1A = wx1[j0], w1B = wx1[j0 + 1];
        float wfA0 = 0.f, wfB0 = 0.f, wfA1 = 0.f, wfB1 = 0.f;
        if (DEC) {
            wfA0 = wfc[j0];      wfB0 = wfc[j0 + 1];
            wfA1 = wfc[64 + j0]; wfB1 = wfc[64 + j0 + 1];
        }
        uint32_t colb = ((uint32_t)(jb * 16 + (lane & 3) * 4)) ^ (q << 4);
#pragma unroll
        for (int i = 0; i < 2; i++) {
            int e = i * 2;
            float x0 = x[i].x, x1 = x[i].y;

            float gi = d[0][e] + fmaf(x1, w1A.x, fmaf(x0, w0A.x, bcA.x));
            float gf = d[1][e] + fmaf(x1, w1A.y, fmaf(x0, w0A.y, bcA.y));
            float gg = d[2][e] + fmaf(x1, w1A.z, fmaf(x0, w0A.z, bcA.z));
            float go = d[3][e] + fmaf(x1, w1A.w, fmaf(x0, w0A.w, bcA.w));
            float c0 = fmaf(fsig(gf), c[i][jb * 2], fsig(gi) * tanh_a(gg));
            c[i][jb * 2] = c0;
            float h0 = fsig(go) * tanh_a(c0);

            gi = d[0][e + 1] + fmaf(x1, w1B.x, fmaf(x0, w0B.x, bcB.x));
            gf = d[1][e + 1] + fmaf(x1, w1B.y, fmaf(x0, w0B.y, bcB.y));
            gg = d[2][e + 1] + fmaf(x1, w1B.z, fmaf(x0, w0B.z, bcB.z));
            go = d[3][e + 1] + fmaf(x1, w1B.w, fmaf(x0, w0B.w, bcB.w));
            float c1 = fmaf(fsig(gf), c[i][jb * 2 + 1], fsig(gi) * tanh_a(gg));
            c[i][jb * 2 + 1] = c1;
            float h1 = fsig(go) * tanh_a(c1);

            if (DEC) {
                fc0[i] = fmaf(h0, wfA0, fmaf(h1, wfB0, fc0[i]));
                fc1[i] = fmaf(h0, wfA1, fmaf(h1, wfB1, fc1[i]));
            }

            // fp16 hi/lo split, pack j-pair, STS into A buffer (swizzled)
            __half hh0 = __float2half_rn(h0);
            __half hh1 = __float2half_rn(h1);
            __half hl0 = __float2half_rn(h0 - __half2float(hh0));
            __half hl1 = __float2half_rn(h1 - __half2float(hh1));
            uint32_t hpk = (uint32_t)__half_as_ushort(hh0) |
                           ((uint32_t)__half_as_ushort(hh1) << 16);
            uint32_t lpk = (uint32_t)__half_as_ushort(hl0) |
                           ((uint32_t)__half_as_ushort(hl1) << 16);
            uint32_t rowoff = (q + (uint32_t)i * 8u) * 128u;
            STS32(aHi + rowoff + colb, hpk);
            STS32(aLo + rowoff + colb, lpk);
        }
    }

    if (DEC) {
#pragma unroll
        for (int i = 0; i < 2; i++) {
            fc0[i] += __shfl_xor_sync(0xffffffffu, fc0[i], 1);
            fc0[i] += __shfl_xor_sync(0xffffffffu, fc0[i], 2);
            fc1[i] += __shfl_xor_sync(0xffffffffu, fc1[i], 1);
            fc1[i] += __shfl_xor_sync(0xffffffffu, fc1[i], 2);
            pt[i] = make_float2(fc0[i], fc1[i]);
        }
    }
}

// ---------------- kernel ----------------
__global__ void __launch_bounds__(TPB, 2)
seq2seq_mma16_kernel(const float* __restrict__ input,
                     const float* __restrict__ Wih_enc, const float* __restrict__ Whh_enc,
                     const float* __restrict__ bih_enc, const float* __restrict__ bhh_enc,
                     const float* __restrict__ Wih_dec, const float* __restrict__ Whh_dec,
                     const float* __restrict__ bih_dec, const float* __restrict__ bhh_dec,
                     const float* __restrict__ Wfc,     const float* __restrict__ bfc,
                     float* __restrict__ out, int B, int T) {
    extern __shared__ char smem_raw[];
    char* sm;
    {
        unsigned long long p = (unsigned long long)smem_raw;
        p = (p + 1023ull) & ~1023ull;
        sm = (char*)p;
    }
    uint32_t smu;
    asm("{ .reg .u64 t; cvta.to.shared.u64 t, %1; cvt.u32.u64 %0, t; }" : "=r"(smu) : "l"(sm));

    int tid  = threadIdx.x;
    int wid  = tid >> 5;
    int lane = tid & 31;

    load_phase(sm, Whh_enc, Wih_enc, bih_enc, bhh_enc, tid);
    {
        float* w = (float*)(sm + OFF_WFC);
        for (int i = tid; i < 128; i += TPB) w[i] = Wfc[i];
        if (tid < 2) ((float*)(sm + OFF_BFC))[tid] = bfc[tid];
    }
    for (int i = tid; i < 32768 / 4; i += TPB) ((uint32_t*)(sm + OFF_A))[i] = 0u;
    __syncthreads();

    uint32_t aHi = smu + OFF_A + (uint32_t)wid * 4096u;
    uint32_t aLo = aHi + 2048u;

    float c[2][16];
#pragma unroll
    for (int i = 0; i < 2; i++)
#pragma unroll
        for (int j = 0; j < 16; j++) c[i][j] = 0.0f;

    int q = lane >> 2;
    long rows[2];
    bool rv[2];
#pragma unroll
    for (int i = 0; i < 2; i++) {
        long r = (long)blockIdx.x * 128 + wid * 16 + q + i * 8;
        rv[i] = r < (long)B;
        rows[i] = rv[i] ? r : (long)(B - 1);
    }

    float2 x[2];
    float2 pt[2];

    // ---- encoder ----
#pragma unroll 1
    for (int t = 0; t < T; t++) {
#pragma unroll
        for (int i = 0; i < 2; i++)
            x[i] = *(const float2*)(input + rows[i] * (long)T * 2 + (long)t * 2);
        lstm_step<false>(smu, sm, aHi, aLo, x, c, pt, lane);
    }

    // ---- swap to decoder weights ----
    __syncthreads();
    load_phase(sm, Whh_dec, Wih_dec, bih_dec, bhh_dec, tid);
    __syncthreads();

    float bf0 = ((const float*)(sm + OFF_BFC))[0];
    float bf1 = ((const float*)(sm + OFF_BFC))[1];

    // ---- decoder (x currently = input[:, T-1] = dec_in0) ----
#pragma unroll 1
    for (int t = 0; t < TOUT; t++) {
        lstm_step<true>(smu, sm, aHi, aLo, x, c, pt, lane);
#pragma unroll
        for (int i = 0; i < 2; i++) {
            float p0 = fsig(pt[i].x + bf0);
            float p1 = fsig(pt[i].y + bf1);
            if ((lane & 3) == 0 && rv[i])
                *(float2*)(out + rows[i] * (long)TOUT * 2 + (long)t * 2) = make_float2(p0, p1);
            x[i] = make_float2(p0, p1);
        }
    }
}

extern "C" void kernel_launch(void* const* d_in, const int* in_sizes, int n_in,
                              void* d_out, int out_size) {
    const float* input   = (const float*)d_in[0];
    const float* Wih_enc = (const float*)d_in[1];
    const float* Whh_enc = (const float*)d_in[2];
    const float* bih_enc = (const float*)d_in[3];
    const float* bhh_enc = (const float*)d_in[4];
    const float* Wih_dec = (const float*)d_in[5];
    const float* Whh_dec = (const float*)d_in[6];
    const float* bih_dec = (const float*)d_in[7];
    const float* bhh_dec = (const float*)d_in[8];
    const float* Wfc     = (const float*)d_in[9];
    const float* bfc     = (const float*)d_in[10];
    float* out = (float*)d_out;

    int B = out_size / (TOUT * 2);
    int T = in_sizes[0] / (B * 2);

    cudaFuncSetAttribute(seq2seq_mma16_kernel,
                         cudaFuncAttributeMaxDynamicSharedMemorySize, SMEM_BYTES);

    int grid = (B + 127) / 128;
    seq2seq_mma16_kernel<<<grid, TPB, SMEM_BYTES>>>(
        input, Wih_enc, Whh_enc, bih_enc, bhh_enc,
        Wih_dec, Whh_dec, bih_dec, bhh_dec, Wfc, bfc,
        out, B, T);
}